// round 12
// baseline (speedup 1.0000x reference)
#include <cuda_runtime.h>
#include <math.h>

#define N 1024
#define EPSF 1e-8f

struct __align__(16) Geom {
    float cx, cy, cs, sn, hx, hy, rad, area;
    float x[4], y[4];
};

__device__ Geom d_geomP[N];
__device__ Geom d_geomG[N];
__device__ Geom d_geomGo[N];
__device__ float4 d_ccP[N];
__device__ float4 d_ccG[N];
__device__ float4 d_ccGo[N];
__device__ int d_order[N];
__device__ unsigned int d_maskW[32 * N];   // [w][j]: in-edges to col j from word w (cross-word, i<j)
__device__ unsigned int d_inword[32 * 32]; // [w][b]: out-edges of i=32w+b to j within word w
__device__ float d_pzmin[N], d_pzmax[N], d_pvol[N];
__device__ float d_gzmin[N], d_gzmax[N], d_gvol[N];
// compact kept-gt arrays (written by nms_gs)
__device__ Geom d_geomK[N];
__device__ float4 d_ccK[N];   // cx, cy, rad, vol
__device__ float2 d_zK[N];    // zmin, zmax
__device__ int d_joK[N];      // original gt index
__device__ int d_Scnt;

__device__ __forceinline__ void make_geom(const float* b, Geom& g) {
    float cx = b[0], cy = b[1], dx = b[3], dy = b[4], r = b[6];
    float sn, cs;
    sincosf(r, &sn, &cs);
    float hx = 0.5f * dx, hy = 0.5f * dy;
    g.cx = cx; g.cy = cy; g.cs = cs; g.sn = sn;
    g.hx = hx; g.hy = hy;
    g.rad = 0.5f * sqrtf(dx * dx + dy * dy);
    g.area = dx * dy;
    g.x[0] =  hx * cs - hy * sn + cx;  g.y[0] =  hx * sn + hy * cs + cy;
    g.x[1] =  hx * cs + hy * sn + cx;  g.y[1] =  hx * sn - hy * cs + cy;
    g.x[2] = -hx * cs + hy * sn + cx;  g.y[2] = -hx * sn - hy * cs + cy;
    g.x[3] = -hx * cs - hy * sn + cx;  g.y[3] = -hx * sn + hy * cs + cy;
}

// Sutherland–Hodgman clip of B by A's 4 half-planes (CW rect, interior <= 0).
__device__ float rect_inter_sh(const Geom& A, const Geom& B) {
    float qx[8], qy[8];
    int n = 4;
#pragma unroll
    for (int c = 0; c < 4; c++) { qx[c] = B.x[c]; qy[c] = B.y[c]; }
#pragma unroll
    for (int e = 0; e < 4; e++) {
        float x0 = A.x[e], y0 = A.y[e];
        float ex = A.x[(e + 1) & 3] - x0, ey = A.y[(e + 1) & 3] - y0;
        float rx[8], ry[8];
        int m = 0;
        float sxp = qx[n - 1], syp = qy[n - 1];
        float dp = ex * (syp - y0) - ey * (sxp - x0);
        for (int v = 0; v < n; v++) {
            float cxv = qx[v], cyv = qy[v];
            float dc = ex * (cyv - y0) - ey * (cxv - x0);
            bool inp = dp <= 0.f, inc = dc <= 0.f;
            if (inp != inc) {
                float t = dp / (dp - dc);
                rx[m] = sxp + t * (cxv - sxp);
                ry[m] = syp + t * (cyv - syp);
                m++;
            }
            if (inc) { rx[m] = cxv; ry[m] = cyv; m++; }
            sxp = cxv; syp = cyv; dp = dc;
        }
        n = m;
        if (n == 0) return 0.f;
        for (int v = 0; v < n; v++) { qx[v] = rx[v]; qy[v] = ry[v]; }
    }
    float s2 = 0.f;
    for (int v = 0; v < n; v++) {
        int w = (v + 1 < n) ? (v + 1) : 0;
        s2 += qx[v] * qy[w] - qy[v] * qx[w];
    }
    return 0.5f * fabsf(s2);
}

// ---------------- kernels ----------------

// blocks [0,N): stable descending rank of gt box b + order-space geom write.
// blocks [N,N+8): per-box prep (pred then gt) + zero maskW/inword.
__global__ void prep_rank_kernel(const float* __restrict__ pred,
                                 const float* __restrict__ gt,
                                 const float* __restrict__ scores) {
    int b = blockIdx.x;
    int t = threadIdx.x;
    if (b < N) {
        __shared__ int cnt;
        if (t == 0) cnt = 0;
        __syncthreads();
        float si = scores[b];
        int c = 0;
#pragma unroll
        for (int s = 0; s < 4; s++) {
            int j = t + 256 * s;
            float sj = scores[j];
            c += (sj > si) || (sj == si && j < b);
        }
        c += __shfl_down_sync(0xffffffffu, c, 16);
        c += __shfl_down_sync(0xffffffffu, c, 8);
        c += __shfl_down_sync(0xffffffffu, c, 4);
        c += __shfl_down_sync(0xffffffffu, c, 2);
        c += __shfl_down_sync(0xffffffffu, c, 1);
        if ((t & 31) == 0) atomicAdd(&cnt, c);
        __syncthreads();
        if (t == 0) {
            int r = cnt;
            d_order[r] = b;
            Geom g;
            make_geom(gt + 8 * b, g);
            d_geomGo[r] = g;
            d_ccGo[r] = make_float4(g.cx, g.cy, g.rad, 0.f);
        }
    } else {
        int i = (b - N) * 256 + t;  // 0..2047
#pragma unroll
        for (int k = 0; k < 16; k++)          // zero 32K-word maskW
            d_maskW[i + 2048 * k] = 0u;
        if (i < N) {
            d_inword[i] = 0u;
            make_geom(pred + 7 * i, d_geomP[i]);
            Geom& g = d_geomP[i];
            d_ccP[i] = make_float4(g.cx, g.cy, g.rad, 0.f);
            float z = pred[7 * i + 2], dz = pred[7 * i + 5];
            d_pzmin[i] = z - dz * 0.5f;
            d_pzmax[i] = z + dz * 0.5f;
            d_pvol[i]  = pred[7 * i + 3] * pred[7 * i + 4] * dz;
        } else {
            int j = i - N;
            make_geom(gt + 8 * j, d_geomG[j]);
            Geom& g = d_geomG[j];
            d_ccG[j] = make_float4(g.cx, g.cy, g.rad, 0.f);
            float z = gt[8 * j + 2], dz = gt[8 * j + 5];
            d_gzmin[j] = z - dz * 0.5f;
            d_gzmax[j] = z + dz * 0.5f;
            d_gvol[j]  = gt[8 * j + 3] * gt[8 * j + 4] * dz;
        }
    }
}

// warp-per-row NMS: ballot-compact circle survivors (j>i), concurrent clip,
// edge bits via global atomicOr. No block barriers.
__global__ void __launch_bounds__(256) nms_rows_kernel() {
    __shared__ int s_list[8][256];
    int wid = threadIdx.x >> 5, lane = threadIdx.x & 31;
    int i = blockIdx.x * 8 + wid;
    float4 ci = d_ccGo[i];
    int cnt = 0;
    for (int k0 = i + 1; k0 < N; k0 += 32) {
        int j = k0 + lane;
        bool pass = false;
        if (j < N) {
            float4 cj = d_ccGo[j];
            float dx = ci.x - cj.x, dy = ci.y - cj.y;
            float rr = ci.z + cj.z;
            pass = (dx * dx + dy * dy <= rr * rr);
        }
        unsigned bal = __ballot_sync(0xffffffffu, pass);
        if (pass)
            s_list[wid][cnt + __popc(bal & ((1u << lane) - 1u))] = j;
        cnt += __popc(bal);
    }
    if (cnt == 0) return;
    Geom A = d_geomGo[i];
    for (int p = lane; p < cnt; p += 32) {
        int j = s_list[wid][p];
        Geom B = d_geomGo[j];
        float inter = rect_inter_sh(A, B);
        float un = fmaxf(A.area + B.area - inter, EPSF);
        if (inter / un > 0.1f) {
            int wi = i >> 5;
            if (wi == (j >> 5))
                atomicOr(&d_inword[wi * 32 + (i & 31)], 1u << (j & 31));
            else
                atomicOr(&d_maskW[wi * N + j], 1u << (i & 31));
        }
    }
}

// exact greedy NMS (32-step word Gauss-Seidel, ffs-based in-word resolve)
// + compaction of kept gt.
__global__ void __launch_bounds__(1024, 1) nms_gs_kernel() {
    int j = threadIdx.x;
    int w = j >> 5, lane = j & 31;
    __shared__ unsigned keepw[32];
    __shared__ unsigned s_rows[1024];
    __shared__ int warpoff[32];
    unsigned myrow = d_inword[j];
    s_rows[j] = myrow;
    unsigned nz0 = __ballot_sync(0xffffffffu, myrow != 0u);
    bool sup = false;
    const unsigned* colp = d_maskW + j;
#pragma unroll 1
    for (int w2 = 0; w2 < 32; w2++) {
        unsigned colw = colp[w2 * N];
        if (w == w2) {
            unsigned cur_sup = __ballot_sync(0xffffffffu, sup);
            if (lane == 0) {
                unsigned alive = ~cur_sup;
                unsigned nz = nz0;
                unsigned m;
                // rows[b] only contains bits > b, so ascending ffs order == greedy
                while ((m = alive & nz) != 0u) {
                    int b = __ffs(m) - 1;
                    alive &= ~s_rows[w * 32 + b];
                    nz &= ~(1u << b);
                }
                keepw[w2] = alive;
            }
        }
        __syncthreads();
        sup = sup || ((colw & keepw[w2]) != 0u);
    }
    // compact kept gt boxes
    bool keep = (keepw[w] >> lane) & 1u;
    unsigned wb = __ballot_sync(0xffffffffu, keep);
    if (lane == 0) warpoff[w] = __popc(wb);
    __syncthreads();
    if (j == 0) {
        int acc = 0;
#pragma unroll
        for (int k = 0; k < 32; k++) { int c = warpoff[k]; warpoff[k] = acc; acc += c; }
        d_Scnt = acc;
    }
    __syncthreads();
    if (keep) {
        int pos = warpoff[w] + __popc(wb & ((1u << lane) - 1u));
        int jo = d_order[j];
        d_joK[pos] = jo;
        d_geomK[pos] = d_geomGo[j];
        float4 cc = d_ccGo[j];
        d_ccK[pos] = make_float4(cc.x, cc.y, cc.z, d_gvol[jo]);
        d_zK[pos] = make_float2(d_gzmin[jo], d_gzmax[jo]);
    }
}

// warp-per-row iou3d over compact kept list: ballot-compact survivors,
// concurrent clip, shfl max-reduce on packed key, lane 0 writes outputs.
__global__ void __launch_bounds__(256) iou_rows_kernel(
        const float* __restrict__ labels,
        const float* __restrict__ cls,
        float* __restrict__ out) {
    __shared__ int s_list[8][256];
    int wid = threadIdx.x >> 5, lane = threadIdx.x & 31;
    int i = blockIdx.x * 8 + wid;
    float4 ci = d_ccP[i];
    float amin = d_pzmin[i], amax = d_pzmax[i];
    int S = d_Scnt;
    int cnt = 0;
    for (int k0 = 0; k0 < S; k0 += 32) {
        int k = k0 + lane;
        bool pass = false;
        if (k < S) {
            float2 z = d_zK[k];
            float oh = fminf(amax, z.y) - fmaxf(amin, z.x);
            if (oh > 0.f) {
                float4 cj = d_ccK[k];
                float dx = ci.x - cj.x, dy = ci.y - cj.y;
                float rr = ci.z + cj.z;
                pass = (dx * dx + dy * dy <= rr * rr);
            }
        }
        unsigned bal = __ballot_sync(0xffffffffu, pass);
        if (pass)
            s_list[wid][cnt + __popc(bal & ((1u << lane) - 1u))] = k;
        cnt += __popc(bal);
    }
    unsigned long long best = 0xFFFFFFFFull;  // iou=0.0, j=0
    if (cnt > 0) {
        Geom A = d_geomP[i];
        float va = d_pvol[i];
        for (int p = lane; p < cnt; p += 32) {
            int k = s_list[wid][p];
            Geom B = d_geomK[k];
            float2 z = d_zK[k];
            float oh = fminf(amax, z.y) - fmaxf(amin, z.x);
            float inter = rect_inter_sh(A, B) * oh;
            float un = fmaxf(va + d_ccK[k].w - inter, EPSF);
            float iou = inter / un;
            if (iou > 0.f) {
                unsigned long long key =
                    (((unsigned long long)__float_as_uint(iou)) << 32) |
                    (unsigned long long)(0xFFFFFFFFu - (unsigned)d_joK[k]);
                if (key > best) best = key;
            }
        }
#pragma unroll
        for (int o = 16; o > 0; o >>= 1) {
            unsigned long long v = __shfl_xor_sync(0xffffffffu, best, o);
            if (v > best) best = v;
        }
    }
    if (lane == 0) {
        float mo = __uint_as_float((unsigned)(best >> 32));
        int jb = (int)(0xFFFFFFFFu - (unsigned)(best & 0xFFFFFFFFull));
        mo = (mo > 0.75f) ? 1.0f : ((mo < 0.25f) ? 0.0f : mo);
        float lab = labels[i];
        float cp = 1.f / (1.f + expf(-cls[i]));
        out[i]         = (cp > 0.55f && lab > 0.55f) ? 1.0f : 0.0f;
        out[N + i]     = lab;
        out[2 * N + i] = mo;
        out[3 * N + i] = (float)jb;
    }
}

extern "C" void kernel_launch(void* const* d_in, const int* in_sizes, int n_in,
                              void* d_out, int out_size) {
    const float* labels = (const float*)d_in[0];
    const float* pred   = (const float*)d_in[1];
    const float* gt     = (const float*)d_in[2];
    const float* cls    = (const float*)d_in[3];
    if (n_in >= 3 && in_sizes[1] == 8 * N && in_sizes[2] == 7 * N) {
        pred = (const float*)d_in[2];
        gt   = (const float*)d_in[1];
    }
    float* out = (float*)d_out;

    prep_rank_kernel<<<N + 8, 256>>>(pred, gt, labels);
    nms_rows_kernel<<<N / 8, 256>>>();
    nms_gs_kernel<<<1, 1024>>>();
    iou_rows_kernel<<<N / 8, 256>>>(labels, cls, out);
}

// round 13
// speedup vs baseline: 1.1854x; 1.1854x over previous
#include <cuda_runtime.h>
#include <math.h>

#define N 1024
#define EPSF 1e-8f

struct __align__(16) Geom {
    float cx, cy, cs, sn, hx, hy, rad, area;
    float x[4], y[4];
};

__device__ Geom d_geomP[N];
__device__ Geom d_geomG[N];
__device__ Geom d_geomGo[N];
__device__ float4 d_ccP[N];
__device__ float4 d_ccG[N];
__device__ float4 d_ccGo[N];
__device__ int d_order[N];
__device__ unsigned int d_maskW[32 * N];   // [w][j]: in-edges to col j from word w (cross-word, i<j)
__device__ unsigned int d_inword[32 * 32]; // [w][b]: out-edges of i=32w+b to j within word w
__device__ float d_pzmin[N], d_pzmax[N], d_pvol[N];
__device__ float d_gzmin[N], d_gzmax[N], d_gvol[N];
// compact kept-gt arrays (written by nms_gs)
__device__ Geom d_geomK[N];
__device__ float4 d_ccK[N];   // cx, cy, rad, vol
__device__ float2 d_zK[N];    // zmin, zmax
__device__ int d_joK[N];      // original gt index
__device__ int d_Scnt;

__device__ __forceinline__ void make_geom(const float* b, Geom& g) {
    float cx = b[0], cy = b[1], dx = b[3], dy = b[4], r = b[6];
    float sn, cs;
    sincosf(r, &sn, &cs);
    float hx = 0.5f * dx, hy = 0.5f * dy;
    g.cx = cx; g.cy = cy; g.cs = cs; g.sn = sn;
    g.hx = hx; g.hy = hy;
    g.rad = 0.5f * sqrtf(dx * dx + dy * dy);
    g.area = dx * dy;
    g.x[0] =  hx * cs - hy * sn + cx;  g.y[0] =  hx * sn + hy * cs + cy;
    g.x[1] =  hx * cs + hy * sn + cx;  g.y[1] =  hx * sn - hy * cs + cy;
    g.x[2] = -hx * cs + hy * sn + cx;  g.y[2] = -hx * sn - hy * cs + cy;
    g.x[3] = -hx * cs - hy * sn + cx;  g.y[3] = -hx * sn + hy * cs + cy;
}

// Sutherland–Hodgman clip of B by A's 4 half-planes (CW rect, interior <= 0).
__device__ float rect_inter_sh(const Geom& A, const Geom& B) {
    float qx[8], qy[8];
    int n = 4;
#pragma unroll
    for (int c = 0; c < 4; c++) { qx[c] = B.x[c]; qy[c] = B.y[c]; }
#pragma unroll
    for (int e = 0; e < 4; e++) {
        float x0 = A.x[e], y0 = A.y[e];
        float ex = A.x[(e + 1) & 3] - x0, ey = A.y[(e + 1) & 3] - y0;
        float rx[8], ry[8];
        int m = 0;
        float sxp = qx[n - 1], syp = qy[n - 1];
        float dp = ex * (syp - y0) - ey * (sxp - x0);
        for (int v = 0; v < n; v++) {
            float cxv = qx[v], cyv = qy[v];
            float dc = ex * (cyv - y0) - ey * (cxv - x0);
            bool inp = dp <= 0.f, inc = dc <= 0.f;
            if (inp != inc) {
                float t = dp / (dp - dc);
                rx[m] = sxp + t * (cxv - sxp);
                ry[m] = syp + t * (cyv - syp);
                m++;
            }
            if (inc) { rx[m] = cxv; ry[m] = cyv; m++; }
            sxp = cxv; syp = cyv; dp = dc;
        }
        n = m;
        if (n == 0) return 0.f;
        for (int v = 0; v < n; v++) { qx[v] = rx[v]; qy[v] = ry[v]; }
    }
    float s2 = 0.f;
    for (int v = 0; v < n; v++) {
        int w = (v + 1 < n) ? (v + 1) : 0;
        s2 += qx[v] * qy[w] - qy[v] * qx[w];
    }
    return 0.5f * fabsf(s2);
}

// ---------------- kernels ----------------

// blocks [0,N): stable descending rank of gt box b + order-space geom write.
// blocks [N,N+8): per-box prep (pred then gt) + zero maskW/inword.
__global__ void prep_rank_kernel(const float* __restrict__ pred,
                                 const float* __restrict__ gt,
                                 const float* __restrict__ scores) {
    int b = blockIdx.x;
    int t = threadIdx.x;
    if (b < N) {
        __shared__ int cnt;
        if (t == 0) cnt = 0;
        __syncthreads();
        float si = scores[b];
        int c = 0;
#pragma unroll
        for (int s = 0; s < 4; s++) {
            int j = t + 256 * s;
            float sj = scores[j];
            c += (sj > si) || (sj == si && j < b);
        }
        c += __shfl_down_sync(0xffffffffu, c, 16);
        c += __shfl_down_sync(0xffffffffu, c, 8);
        c += __shfl_down_sync(0xffffffffu, c, 4);
        c += __shfl_down_sync(0xffffffffu, c, 2);
        c += __shfl_down_sync(0xffffffffu, c, 1);
        if ((t & 31) == 0) atomicAdd(&cnt, c);
        __syncthreads();
        if (t == 0) {
            int r = cnt;
            d_order[r] = b;
            Geom g;
            make_geom(gt + 8 * b, g);
            d_geomGo[r] = g;
            d_ccGo[r] = make_float4(g.cx, g.cy, g.rad, 0.f);
        }
    } else {
        int i = (b - N) * 256 + t;  // 0..2047
#pragma unroll
        for (int k = 0; k < 16; k++)          // zero 32K-word maskW
            d_maskW[i + 2048 * k] = 0u;
        if (i < N) {
            d_inword[i] = 0u;
            make_geom(pred + 7 * i, d_geomP[i]);
            Geom& g = d_geomP[i];
            d_ccP[i] = make_float4(g.cx, g.cy, g.rad, 0.f);
            float z = pred[7 * i + 2], dz = pred[7 * i + 5];
            d_pzmin[i] = z - dz * 0.5f;
            d_pzmax[i] = z + dz * 0.5f;
            d_pvol[i]  = pred[7 * i + 3] * pred[7 * i + 4] * dz;
        } else {
            int j = i - N;
            make_geom(gt + 8 * j, d_geomG[j]);
            Geom& g = d_geomG[j];
            d_ccG[j] = make_float4(g.cx, g.cy, g.rad, 0.f);
            float z = gt[8 * j + 2], dz = gt[8 * j + 5];
            d_gzmin[j] = z - dz * 0.5f;
            d_gzmax[j] = z + dz * 0.5f;
            d_gvol[j]  = gt[8 * j + 3] * gt[8 * j + 4] * dz;
        }
    }
}

// block-per-row NMS (128 thr): each warp filters a strided quarter into its
// own smem segment, then clips its own survivors. No block barriers at all.
__global__ void __launch_bounds__(128) nms_rows_kernel() {
    __shared__ int s_list[4][256];
    int wid = threadIdx.x >> 5, lane = threadIdx.x & 31;
    int i = blockIdx.x;
    float4 ci = d_ccGo[i];
    int cnt = 0;
    for (int k0 = i + 1 + wid * 32; k0 < N; k0 += 128) {
        int j = k0 + lane;
        bool pass = false;
        if (j < N) {
            float4 cj = d_ccGo[j];
            float dx = ci.x - cj.x, dy = ci.y - cj.y;
            float rr = ci.z + cj.z;
            pass = (dx * dx + dy * dy <= rr * rr);
        }
        unsigned bal = __ballot_sync(0xffffffffu, pass);
        if (pass)
            s_list[wid][cnt + __popc(bal & ((1u << lane) - 1u))] = j;
        cnt += __popc(bal);
    }
    if (cnt == 0) return;
    Geom A = d_geomGo[i];
    for (int p = lane; p < cnt; p += 32) {
        int j = s_list[wid][p];
        Geom B = d_geomGo[j];
        float inter = rect_inter_sh(A, B);
        float un = fmaxf(A.area + B.area - inter, EPSF);
        if (inter / un > 0.1f) {
            int wi = i >> 5;
            if (wi == (j >> 5))
                atomicOr(&d_inword[wi * 32 + (i & 31)], 1u << (j & 31));
            else
                atomicOr(&d_maskW[wi * N + j], 1u << (i & 31));
        }
    }
}

// exact greedy NMS (32-step word Gauss-Seidel, ffs-based in-word resolve)
// + compaction of kept gt.
__global__ void __launch_bounds__(1024, 1) nms_gs_kernel() {
    int j = threadIdx.x;
    int w = j >> 5, lane = j & 31;
    __shared__ unsigned keepw[32];
    __shared__ unsigned s_rows[1024];
    __shared__ int warpoff[32];
    unsigned myrow = d_inword[j];
    s_rows[j] = myrow;
    unsigned nz0 = __ballot_sync(0xffffffffu, myrow != 0u);
    bool sup = false;
    const unsigned* colp = d_maskW + j;
#pragma unroll 1
    for (int w2 = 0; w2 < 32; w2++) {
        unsigned colw = colp[w2 * N];
        if (w == w2) {
            unsigned cur_sup = __ballot_sync(0xffffffffu, sup);
            if (lane == 0) {
                unsigned alive = ~cur_sup;
                unsigned nz = nz0;
                unsigned m;
                // rows[b] only contains bits > b, so ascending ffs order == greedy
                while ((m = alive & nz) != 0u) {
                    int b = __ffs(m) - 1;
                    alive &= ~s_rows[w * 32 + b];
                    nz &= ~(1u << b);
                }
                keepw[w2] = alive;
            }
        }
        __syncthreads();
        sup = sup || ((colw & keepw[w2]) != 0u);
    }
    // compact kept gt boxes
    bool keep = (keepw[w] >> lane) & 1u;
    unsigned wb = __ballot_sync(0xffffffffu, keep);
    if (lane == 0) warpoff[w] = __popc(wb);
    __syncthreads();
    if (j == 0) {
        int acc = 0;
#pragma unroll
        for (int k = 0; k < 32; k++) { int c = warpoff[k]; warpoff[k] = acc; acc += c; }
        d_Scnt = acc;
    }
    __syncthreads();
    if (keep) {
        int pos = warpoff[w] + __popc(wb & ((1u << lane) - 1u));
        int jo = d_order[j];
        d_joK[pos] = jo;
        d_geomK[pos] = d_geomGo[j];
        float4 cc = d_ccGo[j];
        d_ccK[pos] = make_float4(cc.x, cc.y, cc.z, d_gvol[jo]);
        d_zK[pos] = make_float2(d_gzmin[jo], d_gzmax[jo]);
    }
}

// block-per-row iou3d (128 thr) over compact kept list: warp-autonomous
// filter + clip + shfl reduce; one smem atomicMax per warp; single barrier.
__global__ void __launch_bounds__(128) iou_rows_kernel(
        const float* __restrict__ labels,
        const float* __restrict__ cls,
        float* __restrict__ out) {
    __shared__ int s_list[4][256];
    __shared__ unsigned long long s_best;
    int wid = threadIdx.x >> 5, lane = threadIdx.x & 31;
    int i = blockIdx.x;
    if (threadIdx.x == 0) s_best = 0xFFFFFFFFull;  // iou=0.0, j=0
    float4 ci = d_ccP[i];
    float amin = d_pzmin[i], amax = d_pzmax[i];
    int S = d_Scnt;
    int cnt = 0;
    for (int k0 = wid * 32; k0 < S; k0 += 128) {
        int k = k0 + lane;
        bool pass = false;
        if (k < S) {
            float2 z = d_zK[k];
            float oh = fminf(amax, z.y) - fmaxf(amin, z.x);
            if (oh > 0.f) {
                float4 cj = d_ccK[k];
                float dx = ci.x - cj.x, dy = ci.y - cj.y;
                float rr = ci.z + cj.z;
                pass = (dx * dx + dy * dy <= rr * rr);
            }
        }
        unsigned bal = __ballot_sync(0xffffffffu, pass);
        if (pass)
            s_list[wid][cnt + __popc(bal & ((1u << lane) - 1u))] = k;
        cnt += __popc(bal);
    }
    if (cnt > 0) {
        unsigned long long best = 0xFFFFFFFFull;
        Geom A = d_geomP[i];
        float va = d_pvol[i];
        for (int p = lane; p < cnt; p += 32) {
            int k = s_list[wid][p];
            Geom B = d_geomK[k];
            float2 z = d_zK[k];
            float oh = fminf(amax, z.y) - fmaxf(amin, z.x);
            float inter = rect_inter_sh(A, B) * oh;
            float un = fmaxf(va + d_ccK[k].w - inter, EPSF);
            float iou = inter / un;
            if (iou > 0.f) {
                unsigned long long key =
                    (((unsigned long long)__float_as_uint(iou)) << 32) |
                    (unsigned long long)(0xFFFFFFFFu - (unsigned)d_joK[k]);
                if (key > best) best = key;
            }
        }
#pragma unroll
        for (int o = 16; o > 0; o >>= 1) {
            unsigned long long v = __shfl_xor_sync(0xffffffffu, best, o);
            if (v > best) best = v;
        }
        if (lane == 0 && best > 0xFFFFFFFFull) atomicMax(&s_best, best);
    }
    __syncthreads();
    if (threadIdx.x == 0) {
        unsigned long long key = s_best;
        float mo = __uint_as_float((unsigned)(key >> 32));
        int jb = (int)(0xFFFFFFFFu - (unsigned)(key & 0xFFFFFFFFull));
        mo = (mo > 0.75f) ? 1.0f : ((mo < 0.25f) ? 0.0f : mo);
        float lab = labels[i];
        float cp = 1.f / (1.f + expf(-cls[i]));
        out[i]         = (cp > 0.55f && lab > 0.55f) ? 1.0f : 0.0f;
        out[N + i]     = lab;
        out[2 * N + i] = mo;
        out[3 * N + i] = (float)jb;
    }
}

extern "C" void kernel_launch(void* const* d_in, const int* in_sizes, int n_in,
                              void* d_out, int out_size) {
    const float* labels = (const float*)d_in[0];
    const float* pred   = (const float*)d_in[1];
    const float* gt     = (const float*)d_in[2];
    const float* cls    = (const float*)d_in[3];
    if (n_in >= 3 && in_sizes[1] == 8 * N && in_sizes[2] == 7 * N) {
        pred = (const float*)d_in[2];
        gt   = (const float*)d_in[1];
    }
    float* out = (float*)d_out;

    prep_rank_kernel<<<N + 8, 256>>>(pred, gt, labels);
    nms_rows_kernel<<<N, 128>>>();
    nms_gs_kernel<<<1, 1024>>>();
    iou_rows_kernel<<<N, 128>>>(labels, cls, out);
}

// round 15
// speedup vs baseline: 1.3917x; 1.1740x over previous
#include <cuda_runtime.h>
#include <math.h>

#define N 1024
#define EPSF 1e-8f

struct __align__(16) Geom {
    float cx, cy, cs, sn, hx, hy, rad, area;
    float x[4], y[4];
};

__device__ Geom d_geomP[N];
__device__ Geom d_geomG[N];
__device__ Geom d_geomGo[N];
__device__ float4 d_ccP[N];
__device__ float4 d_ccG[N];
__device__ float4 d_ccGo[N];
__device__ int d_order[N];
__device__ unsigned int d_maskW[32 * N];   // [w][j]: in-edges to col j from word w (cross-word, i<j)
__device__ unsigned int d_inword[32 * 32]; // [w][b]: out-edges of i=32w+b to j within word w
__device__ float d_pzmin[N], d_pzmax[N], d_pvol[N];
__device__ float d_gzmin[N], d_gzmax[N], d_gvol[N];
// compact kept-gt arrays (written by nms_gs)
__device__ Geom d_geomK[N];
__device__ float4 d_ccK[N];   // cx, cy, rad, vol
__device__ float2 d_zK[N];    // zmin, zmax
__device__ int d_joK[N];      // original gt index
__device__ int d_Scnt;

__device__ __forceinline__ void make_geom(const float* b, Geom& g) {
    float cx = b[0], cy = b[1], dx = b[3], dy = b[4], r = b[6];
    float sn, cs;
    sincosf(r, &sn, &cs);
    float hx = 0.5f * dx, hy = 0.5f * dy;
    g.cx = cx; g.cy = cy; g.cs = cs; g.sn = sn;
    g.hx = hx; g.hy = hy;
    g.rad = 0.5f * sqrtf(dx * dx + dy * dy);
    g.area = dx * dy;
    g.x[0] =  hx * cs - hy * sn + cx;  g.y[0] =  hx * sn + hy * cs + cy;
    g.x[1] =  hx * cs + hy * sn + cx;  g.y[1] =  hx * sn - hy * cs + cy;
    g.x[2] = -hx * cs + hy * sn + cx;  g.y[2] = -hx * sn - hy * cs + cy;
    g.x[3] = -hx * cs - hy * sn + cx;  g.y[3] = -hx * sn + hy * cs + cy;
}

// Sum over edges of P of (x1*y2 - x2*y1) for the sub-segment of each edge
// lying inside rect C (Liang-Barsky interval clip in C's local frame).
// Endpoints evaluated in a common frame translated by (-ox,-oy).
__device__ __forceinline__ float edge_contrib(const Geom& P, const Geom& C,
                                              float ox, float oy) {
    float acc = 0.f;
#pragma unroll
    for (int e = 0; e < 4; e++) {
        float pxg = P.x[e],           pyg = P.y[e];
        float qxg = P.x[(e + 1) & 3], qyg = P.y[(e + 1) & 3];
        // endpoints in C-local frame
        float rx = pxg - C.cx, ry = pyg - C.cy;
        float px =  rx * C.cs + ry * C.sn;
        float py = -rx * C.sn + ry * C.cs;
        float sx = qxg - C.cx, sy = qyg - C.cy;
        float qx =  sx * C.cs + sy * C.sn;
        float qy = -sx * C.sn + sy * C.cs;
        float dx = qx - px, dy = qy - py;
        float rdx = 1.f / dx, rdy = 1.f / dy;   // +-inf ok for axis-parallel
        float ta = ( C.hx - px) * rdx, tb = (-C.hx - px) * rdx;
        float tc = ( C.hy - py) * rdy, td = (-C.hy - py) * rdy;
        float t0 = fmaxf(fmaxf(fminf(ta, tb), fminf(tc, td)), 0.f);
        float t1 = fminf(fminf(fmaxf(ta, tb), fmaxf(tc, td)), 1.f);
        if (t1 > t0) {
            float gx = qxg - pxg, gy = qyg - pyg;
            float bx = pxg - ox, by = pyg - oy;
            float x1 = bx + t0 * gx, y1 = by + t0 * gy;
            float x2 = bx + t1 * gx, y2 = by + t1 * gy;
            acc += x1 * y2 - x2 * y1;
        }
    }
    return acc;
}

// Exact convex intersection area via Green's theorem:
// boundary(A^B) = (dA in B) u (dB in A); contributions order-independent.
__device__ __forceinline__ float rect_inter_bi(const Geom& A, const Geom& B) {
    float s = edge_contrib(A, B, A.cx, A.cy) + edge_contrib(B, A, A.cx, A.cy);
    return 0.5f * fabsf(s);
}

// ---------------- kernels ----------------

// blocks [0,N): stable descending rank of gt box b + order-space geom write.
// blocks [N,N+8): per-box prep (pred then gt) + zero maskW/inword.
__global__ void prep_rank_kernel(const float* __restrict__ pred,
                                 const float* __restrict__ gt,
                                 const float* __restrict__ scores) {
    int b = blockIdx.x;
    int t = threadIdx.x;
    if (b < N) {
        __shared__ int cnt;
        if (t == 0) cnt = 0;
        __syncthreads();
        float si = scores[b];
        int c = 0;
#pragma unroll
        for (int s = 0; s < 4; s++) {
            int j = t + 256 * s;
            float sj = scores[j];
            c += (sj > si) || (sj == si && j < b);
        }
        c += __shfl_down_sync(0xffffffffu, c, 16);
        c += __shfl_down_sync(0xffffffffu, c, 8);
        c += __shfl_down_sync(0xffffffffu, c, 4);
        c += __shfl_down_sync(0xffffffffu, c, 2);
        c += __shfl_down_sync(0xffffffffu, c, 1);
        if ((t & 31) == 0) atomicAdd(&cnt, c);
        __syncthreads();
        if (t == 0) {
            int r = cnt;
            d_order[r] = b;
            Geom g;
            make_geom(gt + 8 * b, g);
            d_geomGo[r] = g;
            d_ccGo[r] = make_float4(g.cx, g.cy, g.rad, 0.f);
        }
    } else {
        int i = (b - N) * 256 + t;  // 0..2047
#pragma unroll
        for (int k = 0; k < 16; k++)          // zero 32K-word maskW
            d_maskW[i + 2048 * k] = 0u;
        if (i < N) {
            d_inword[i] = 0u;
            make_geom(pred + 7 * i, d_geomP[i]);
            Geom& g = d_geomP[i];
            d_ccP[i] = make_float4(g.cx, g.cy, g.rad, 0.f);
            float z = pred[7 * i + 2], dz = pred[7 * i + 5];
            d_pzmin[i] = z - dz * 0.5f;
            d_pzmax[i] = z + dz * 0.5f;
            d_pvol[i]  = pred[7 * i + 3] * pred[7 * i + 4] * dz;
        } else {
            int j = i - N;
            make_geom(gt + 8 * j, d_geomG[j]);
            Geom& g = d_geomG[j];
            d_ccG[j] = make_float4(g.cx, g.cy, g.rad, 0.f);
            float z = gt[8 * j + 2], dz = gt[8 * j + 5];
            d_gzmin[j] = z - dz * 0.5f;
            d_gzmax[j] = z + dz * 0.5f;
            d_gvol[j]  = gt[8 * j + 3] * gt[8 * j + 4] * dz;
        }
    }
}

// block-per-row NMS (128 thr): each warp filters a strided quarter into its
// own smem segment, then clips its own survivors. No block barriers at all.
__global__ void __launch_bounds__(128) nms_rows_kernel() {
    __shared__ int s_list[4][256];
    int wid = threadIdx.x >> 5, lane = threadIdx.x & 31;
    int i = blockIdx.x;
    Geom A = d_geomGo[i];             // hoisted: overlaps with filter scan
    float4 ci = d_ccGo[i];
    int cnt = 0;
    for (int k0 = i + 1 + wid * 32; k0 < N; k0 += 128) {
        int j = k0 + lane;
        bool pass = false;
        if (j < N) {
            float4 cj = d_ccGo[j];
            float dx = ci.x - cj.x, dy = ci.y - cj.y;
            float rr = ci.z + cj.z;
            pass = (dx * dx + dy * dy <= rr * rr);
        }
        unsigned bal = __ballot_sync(0xffffffffu, pass);
        if (pass)
            s_list[wid][cnt + __popc(bal & ((1u << lane) - 1u))] = j;
        cnt += __popc(bal);
    }
    if (cnt == 0) return;
    for (int p = lane; p < cnt; p += 32) {
        int j = s_list[wid][p];
        Geom B = d_geomGo[j];
        float inter = rect_inter_bi(A, B);
        float un = fmaxf(A.area + B.area - inter, EPSF);
        if (inter / un > 0.1f) {
            int wi = i >> 5;
            if (wi == (j >> 5))
                atomicOr(&d_inword[wi * 32 + (i & 31)], 1u << (j & 31));
            else
                atomicOr(&d_maskW[wi * N + j], 1u << (i & 31));
        }
    }
}

// exact greedy NMS (32-step word Gauss-Seidel, ffs-based in-word resolve)
// + compaction of kept gt.
__global__ void __launch_bounds__(1024, 1) nms_gs_kernel() {
    int j = threadIdx.x;
    int w = j >> 5, lane = j & 31;
    __shared__ unsigned keepw[32];
    __shared__ unsigned s_rows[1024];
    __shared__ int warpoff[32];
    unsigned myrow = d_inword[j];
    s_rows[j] = myrow;
    unsigned nz0 = __ballot_sync(0xffffffffu, myrow != 0u);
    bool sup = false;
    const unsigned* colp = d_maskW + j;
#pragma unroll 1
    for (int w2 = 0; w2 < 32; w2++) {
        unsigned colw = colp[w2 * N];
        if (w == w2) {
            unsigned cur_sup = __ballot_sync(0xffffffffu, sup);
            if (lane == 0) {
                unsigned alive = ~cur_sup;
                unsigned nz = nz0;
                unsigned m;
                // rows[b] only contains bits > b, so ascending ffs order == greedy
                while ((m = alive & nz) != 0u) {
                    int b = __ffs(m) - 1;
                    alive &= ~s_rows[w * 32 + b];
                    nz &= ~(1u << b);
                }
                keepw[w2] = alive;
            }
        }
        __syncthreads();
        sup = sup || ((colw & keepw[w2]) != 0u);
    }
    // compact kept gt boxes
    bool keep = (keepw[w] >> lane) & 1u;
    unsigned wb = __ballot_sync(0xffffffffu, keep);
    if (lane == 0) warpoff[w] = __popc(wb);
    __syncthreads();
    if (j == 0) {
        int acc = 0;
#pragma unroll
        for (int k = 0; k < 32; k++) { int c = warpoff[k]; warpoff[k] = acc; acc += c; }
        d_Scnt = acc;
    }
    __syncthreads();
    if (keep) {
        int pos = warpoff[w] + __popc(wb & ((1u << lane) - 1u));
        int jo = d_order[j];
        d_joK[pos] = jo;
        d_geomK[pos] = d_geomGo[j];
        float4 cc = d_ccGo[j];
        d_ccK[pos] = make_float4(cc.x, cc.y, cc.z, d_gvol[jo]);
        d_zK[pos] = make_float2(d_gzmin[jo], d_gzmax[jo]);
    }
}

// block-per-row iou3d (128 thr) over compact kept list: warp-autonomous
// filter + clip + shfl reduce; one smem atomicMax per warp; single barrier.
__global__ void __launch_bounds__(128) iou_rows_kernel(
        const float* __restrict__ labels,
        const float* __restrict__ cls,
        float* __restrict__ out) {
    __shared__ int s_list[4][256];
    __shared__ unsigned long long s_best;
    int wid = threadIdx.x >> 5, lane = threadIdx.x & 31;
    int i = blockIdx.x;
    if (threadIdx.x == 0) s_best = 0xFFFFFFFFull;  // iou=0.0, j=0
    Geom A = d_geomP[i];              // hoisted: overlaps with filter scan
    float va = d_pvol[i];
    float4 ci = d_ccP[i];
    float amin = d_pzmin[i], amax = d_pzmax[i];
    int S = d_Scnt;
    int cnt = 0;
    for (int k0 = wid * 32; k0 < S; k0 += 128) {
        int k = k0 + lane;
        bool pass = false;
        if (k < S) {
            float2 z = d_zK[k];
            float oh = fminf(amax, z.y) - fmaxf(amin, z.x);
            if (oh > 0.f) {
                float4 cj = d_ccK[k];
                float dx = ci.x - cj.x, dy = ci.y - cj.y;
                float rr = ci.z + cj.z;
                pass = (dx * dx + dy * dy <= rr * rr);
            }
        }
        unsigned bal = __ballot_sync(0xffffffffu, pass);
        if (pass)
            s_list[wid][cnt + __popc(bal & ((1u << lane) - 1u))] = k;
        cnt += __popc(bal);
    }
    if (cnt > 0) {
        unsigned long long best = 0xFFFFFFFFull;
        for (int p = lane; p < cnt; p += 32) {
            int k = s_list[wid][p];
            Geom B = d_geomK[k];
            float2 z = d_zK[k];
            float oh = fminf(amax, z.y) - fmaxf(amin, z.x);
            float inter = rect_inter_bi(A, B) * oh;
            float un = fmaxf(va + d_ccK[k].w - inter, EPSF);
            float iou = inter / un;
            if (iou > 0.f) {
                unsigned long long key =
                    (((unsigned long long)__float_as_uint(iou)) << 32) |
                    (unsigned long long)(0xFFFFFFFFu - (unsigned)d_joK[k]);
                if (key > best) best = key;
            }
        }
#pragma unroll
        for (int o = 16; o > 0; o >>= 1) {
            unsigned long long v = __shfl_xor_sync(0xffffffffu, best, o);
            if (v > best) best = v;
        }
        if (lane == 0 && best > 0xFFFFFFFFull) atomicMax(&s_best, best);
    }
    __syncthreads();
    if (threadIdx.x == 0) {
        unsigned long long key = s_best;
        float mo = __uint_as_float((unsigned)(key >> 32));
        int jb = (int)(0xFFFFFFFFu - (unsigned)(key & 0xFFFFFFFFull));
        mo = (mo > 0.75f) ? 1.0f : ((mo < 0.25f) ? 0.0f : mo);
        float lab = labels[i];
        float cp = 1.f / (1.f + expf(-cls[i]));
        out[i]         = (cp > 0.55f && lab > 0.55f) ? 1.0f : 0.0f;
        out[N + i]     = lab;
        out[2 * N + i] = mo;
        out[3 * N + i] = (float)jb;
    }
}

extern "C" void kernel_launch(void* const* d_in, const int* in_sizes, int n_in,
                              void* d_out, int out_size) {
    const float* labels = (const float*)d_in[0];
    const float* pred   = (const float*)d_in[1];
    const float* gt     = (const float*)d_in[2];
    const float* cls    = (const float*)d_in[3];
    if (n_in >= 3 && in_sizes[1] == 8 * N && in_sizes[2] == 7 * N) {
        pred = (const float*)d_in[2];
        gt   = (const float*)d_in[1];
    }
    float* out = (float*)d_out;

    prep_rank_kernel<<<N + 8, 256>>>(pred, gt, labels);
    nms_rows_kernel<<<N, 128>>>();
    nms_gs_kernel<<<1, 1024>>>();
    iou_rows_kernel<<<N, 128>>>(labels, cls, out);
}

// round 17
// speedup vs baseline: 1.5000x; 1.0779x over previous
#include <cuda_runtime.h>
#include <math.h>

#define N 1024
#define EPSF 1e-8f

struct __align__(16) Geom {
    float cx, cy, cs, sn, hx, hy, rad, area;
    float x[4], y[4];
};

__device__ Geom d_geomP[N];
__device__ Geom d_geomG[N];
__device__ Geom d_geomGo[N];
__device__ float4 d_ccP[N];
__device__ float4 d_ccG[N];
__device__ float4 d_ccGo[N];
__device__ int d_order[N];
__device__ unsigned int d_maskW[32 * N];   // [w][j]: in-edges to col j from word w (cross-word)
__device__ unsigned int d_inword[32 * 32]; // [w][b]: out-edges of i=32w+b within word w
__device__ unsigned int d_nextw[32 * 32];  // [w][b]: out-edges of i=32w+b to word w+1 (w even only)
__device__ float d_pzmin[N], d_pzmax[N], d_pvol[N];
__device__ float d_gzmin[N], d_gzmax[N], d_gvol[N];
// compact kept-gt arrays (written by nms_gs)
__device__ Geom d_geomK[N];
__device__ float4 d_ccK[N];   // cx, cy, rad, vol
__device__ float2 d_zK[N];    // zmin, zmax
__device__ int d_joK[N];      // original gt index
__device__ int d_Scnt;

__device__ __forceinline__ void make_geom(const float* b, Geom& g) {
    float cx = b[0], cy = b[1], dx = b[3], dy = b[4], r = b[6];
    float sn, cs;
    sincosf(r, &sn, &cs);
    float hx = 0.5f * dx, hy = 0.5f * dy;
    g.cx = cx; g.cy = cy; g.cs = cs; g.sn = sn;
    g.hx = hx; g.hy = hy;
    g.rad = 0.5f * sqrtf(dx * dx + dy * dy);
    g.area = dx * dy;
    g.x[0] =  hx * cs - hy * sn + cx;  g.y[0] =  hx * sn + hy * cs + cy;
    g.x[1] =  hx * cs + hy * sn + cx;  g.y[1] =  hx * sn - hy * cs + cy;
    g.x[2] = -hx * cs + hy * sn + cx;  g.y[2] = -hx * sn - hy * cs + cy;
    g.x[3] = -hx * cs - hy * sn + cx;  g.y[3] = -hx * sn + hy * cs + cy;
}

// Sum over edges of P of (x1*y2 - x2*y1) for the sub-segment of each edge
// inside rect C (Liang-Barsky in C's local frame), common frame at (ox,oy).
__device__ __forceinline__ float edge_contrib(const Geom& P, const Geom& C,
                                              float ox, float oy) {
    float acc = 0.f;
#pragma unroll
    for (int e = 0; e < 4; e++) {
        float pxg = P.x[e],           pyg = P.y[e];
        float qxg = P.x[(e + 1) & 3], qyg = P.y[(e + 1) & 3];
        float rx = pxg - C.cx, ry = pyg - C.cy;
        float px =  rx * C.cs + ry * C.sn;
        float py = -rx * C.sn + ry * C.cs;
        float sx = qxg - C.cx, sy = qyg - C.cy;
        float qx =  sx * C.cs + sy * C.sn;
        float qy = -sx * C.sn + sy * C.cs;
        float dx = qx - px, dy = qy - py;
        float rdx = 1.f / dx, rdy = 1.f / dy;
        float ta = ( C.hx - px) * rdx, tb = (-C.hx - px) * rdx;
        float tc = ( C.hy - py) * rdy, td = (-C.hy - py) * rdy;
        float t0 = fmaxf(fmaxf(fminf(ta, tb), fminf(tc, td)), 0.f);
        float t1 = fminf(fminf(fmaxf(ta, tb), fmaxf(tc, td)), 1.f);
        if (t1 > t0) {
            float gx = qxg - pxg, gy = qyg - pyg;
            float bx = pxg - ox, by = pyg - oy;
            float x1 = bx + t0 * gx, y1 = by + t0 * gy;
            float x2 = bx + t1 * gx, y2 = by + t1 * gy;
            acc += x1 * y2 - x2 * y1;
        }
    }
    return acc;
}

__device__ __forceinline__ float rect_inter_bi(const Geom& A, const Geom& B) {
    float s = edge_contrib(A, B, A.cx, A.cy) + edge_contrib(B, A, A.cx, A.cy);
    return 0.5f * fabsf(s);
}

// ---------------- kernels ----------------

__global__ void prep_rank_kernel(const float* __restrict__ pred,
                                 const float* __restrict__ gt,
                                 const float* __restrict__ scores) {
    int b = blockIdx.x;
    int t = threadIdx.x;
    if (b < N) {
        __shared__ int cnt;
        if (t == 0) cnt = 0;
        __syncthreads();
        float si = scores[b];
        int c = 0;
#pragma unroll
        for (int s = 0; s < 4; s++) {
            int j = t + 256 * s;
            float sj = scores[j];
            c += (sj > si) || (sj == si && j < b);
        }
        c += __shfl_down_sync(0xffffffffu, c, 16);
        c += __shfl_down_sync(0xffffffffu, c, 8);
        c += __shfl_down_sync(0xffffffffu, c, 4);
        c += __shfl_down_sync(0xffffffffu, c, 2);
        c += __shfl_down_sync(0xffffffffu, c, 1);
        if ((t & 31) == 0) atomicAdd(&cnt, c);
        __syncthreads();
        if (t == 0) {
            int r = cnt;
            d_order[r] = b;
            Geom g;
            make_geom(gt + 8 * b, g);
            d_geomGo[r] = g;
            d_ccGo[r] = make_float4(g.cx, g.cy, g.rad, 0.f);
        }
    } else {
        int i = (b - N) * 256 + t;  // 0..2047
#pragma unroll
        for (int k = 0; k < 16; k++)
            d_maskW[i + 2048 * k] = 0u;
        if (i < N) {
            d_inword[i] = 0u;
            d_nextw[i] = 0u;
            make_geom(pred + 7 * i, d_geomP[i]);
            Geom& g = d_geomP[i];
            d_ccP[i] = make_float4(g.cx, g.cy, g.rad, 0.f);
            float z = pred[7 * i + 2], dz = pred[7 * i + 5];
            d_pzmin[i] = z - dz * 0.5f;
            d_pzmax[i] = z + dz * 0.5f;
            d_pvol[i]  = pred[7 * i + 3] * pred[7 * i + 4] * dz;
        } else {
            int j = i - N;
            make_geom(gt + 8 * j, d_geomG[j]);
            Geom& g = d_geomG[j];
            d_ccG[j] = make_float4(g.cx, g.cy, g.rad, 0.f);
            float z = gt[8 * j + 2], dz = gt[8 * j + 5];
            d_gzmin[j] = z - dz * 0.5f;
            d_gzmax[j] = z + dz * 0.5f;
            d_gvol[j]  = gt[8 * j + 3] * gt[8 * j + 4] * dz;
        }
    }
}

// block-per-row NMS (128 thr): warp-autonomous filter (prefetch-pipelined)
// then clip own survivors. No block barriers.
__global__ void __launch_bounds__(128, 6) nms_rows_kernel() {
    __shared__ int s_list[4][256];
    int wid = threadIdx.x >> 5, lane = threadIdx.x & 31;
    int i = blockIdx.x;
    Geom A = d_geomGo[i];
    float4 ci = d_ccGo[i];
    int cnt = 0;
    int k0 = i + 1 + wid * 32;
    int j = k0 + lane;
    bool v = (j < N);
    float4 cj;
    if (v) cj = d_ccGo[j];
    for (; k0 < N; k0 += 128) {
        int jn = k0 + 128 + lane;
        bool vn = (jn < N);
        float4 cjn;
        if (vn) cjn = d_ccGo[jn];          // prefetch next iteration
        bool pass = false;
        if (v) {
            float dx = ci.x - cj.x, dy = ci.y - cj.y;
            float rr = ci.z + cj.z;
            pass = (dx * dx + dy * dy <= rr * rr);
        }
        unsigned bal = __ballot_sync(0xffffffffu, pass);
        if (pass)
            s_list[wid][cnt + __popc(bal & ((1u << lane) - 1u))] = k0 + lane;
        cnt += __popc(bal);
        cj = cjn; v = vn;
    }
    if (cnt == 0) return;
    for (int p = lane; p < cnt; p += 32) {
        int j2 = s_list[wid][p];
        Geom B = d_geomGo[j2];
        float inter = rect_inter_bi(A, B);
        float un = fmaxf(A.area + B.area - inter, EPSF);
        if (inter / un > 0.1f) {
            int wi = i >> 5, wj = j2 >> 5;
            if (wi == wj)
                atomicOr(&d_inword[i], 1u << (j2 & 31));
            else if (wj == wi + 1 && !(wi & 1))
                atomicOr(&d_nextw[i], 1u << (j2 & 31));
            else
                atomicOr(&d_maskW[wi * N + j2], 1u << (i & 31));
        }
    }
}

// exact greedy NMS: 16 steps of 64-column Gauss-Seidel. Warp W owns cols
// 64W+l (word 2W) and 64W+32+l (word 2W+1) so both sup words are one warp.
__global__ void __launch_bounds__(512, 1) nms_gs_kernel() {
    int t = threadIdx.x;
    int W = t >> 5, lane = t & 31;
    int colA = W * 64 + lane;        // word 2W
    int colB = colA + 32;            // word 2W+1
    __shared__ unsigned keepw[32];
    __shared__ unsigned long long s_row[1024];
    __shared__ unsigned long long s_nz[16];
    __shared__ int warpoff[32];
    unsigned long long rowA = (unsigned long long)d_inword[colA] |
                              ((unsigned long long)d_nextw[colA] << 32);
    unsigned long long rowB = ((unsigned long long)d_inword[colB]) << 32;
    s_row[colA] = rowA;
    s_row[colB] = rowB;
    unsigned nzA = __ballot_sync(0xffffffffu, rowA != 0ull);
    unsigned nzB = __ballot_sync(0xffffffffu, rowB != 0ull);
    if (lane == 0)
        s_nz[W] = (unsigned long long)nzA | ((unsigned long long)nzB << 32);
    bool supA = false, supB = false;
    const unsigned* mpA = d_maskW + colA;
    const unsigned* mpB = d_maskW + colB;
    __syncthreads();
#pragma unroll 1
    for (int step = 0; step < 16; step++) {
        unsigned mA0 = mpA[(2 * step) * N],     mA1 = mpA[(2 * step + 1) * N];
        unsigned mB0 = mpB[(2 * step) * N],     mB1 = mpB[(2 * step + 1) * N];
        if (W == step) {
            unsigned bA = __ballot_sync(0xffffffffu, supA);
            unsigned bB = __ballot_sync(0xffffffffu, supB);
            if (lane == 0) {
                unsigned long long alive =
                    ~((unsigned long long)bA | ((unsigned long long)bB << 32));
                unsigned long long nz = s_nz[W];
                unsigned long long m;
                // row(b) only contains bits > b -> ascending order == greedy
                while ((m = alive & nz) != 0ull) {
                    int b = __ffsll(m) - 1;
                    alive &= ~s_row[W * 64 + b];
                    nz &= ~(1ull << b);
                }
                keepw[2 * step]     = (unsigned)alive;
                keepw[2 * step + 1] = (unsigned)(alive >> 32);
            }
        }
        __syncthreads();
        unsigned k0 = keepw[2 * step], k1 = keepw[2 * step + 1];
        supA = supA || (((mA0 & k0) | (mA1 & k1)) != 0u);
        supB = supB || (((mB0 & k0) | (mB1 & k1)) != 0u);
    }
    // word-prefix offsets (warp 0) then per-thread compaction of 2 columns
    if (t < 32) {
        int c = __popc(keepw[t]);
        int x = c;
#pragma unroll
        for (int off = 1; off < 32; off <<= 1) {
            int y = __shfl_up_sync(0xffffffffu, x, off);
            if (lane >= off) x += y;
        }
        warpoff[t] = x - c;
        if (t == 31) d_Scnt = x;
    }
    __syncthreads();
#pragma unroll
    for (int h = 0; h < 2; h++) {
        int col = (h == 0) ? colA : colB;
        int w = col >> 5, bit = col & 31;
        unsigned kw = keepw[w];
        if ((kw >> bit) & 1u) {
            int pos = warpoff[w] + __popc(kw & ((1u << bit) - 1u));
            int jo = d_order[col];
            d_joK[pos] = jo;
            d_geomK[pos] = d_geomGo[col];
            float4 cc = d_ccGo[col];
            d_ccK[pos] = make_float4(cc.x, cc.y, cc.z, d_gvol[jo]);
            d_zK[pos] = make_float2(d_gzmin[jo], d_gzmax[jo]);
        }
    }
}

// block-per-row iou3d (128 thr) over compact kept list: prefetch-pipelined
// filter, concurrent clip, shfl reduce, one smem atomicMax per warp.
__global__ void __launch_bounds__(128, 6) iou_rows_kernel(
        const float* __restrict__ labels,
        const float* __restrict__ cls,
        float* __restrict__ out) {
    __shared__ int s_list[4][256];
    __shared__ unsigned long long s_best;
    int wid = threadIdx.x >> 5, lane = threadIdx.x & 31;
    int i = blockIdx.x;
    if (threadIdx.x == 0) s_best = 0xFFFFFFFFull;  // iou=0.0, j=0
    Geom A = d_geomP[i];
    float va = d_pvol[i];
    float4 ci = d_ccP[i];
    float amin = d_pzmin[i], amax = d_pzmax[i];
    int S = d_Scnt;
    int cnt = 0;
    int k = wid * 32 + lane;
    bool v = (k < S);
    float2 z; float4 cj;
    if (v) { z = d_zK[k]; cj = d_ccK[k]; }
    for (int k0 = wid * 32; k0 < S; k0 += 128) {
        int kn = k0 + 128 + lane;
        bool vn = (kn < S);
        float2 zn; float4 cjn;
        if (vn) { zn = d_zK[kn]; cjn = d_ccK[kn]; }   // prefetch
        bool pass = false;
        if (v) {
            float oh = fminf(amax, z.y) - fmaxf(amin, z.x);
            if (oh > 0.f) {
                float dx = ci.x - cj.x, dy = ci.y - cj.y;
                float rr = ci.z + cj.z;
                pass = (dx * dx + dy * dy <= rr * rr);
            }
        }
        unsigned bal = __ballot_sync(0xffffffffu, pass);
        if (pass)
            s_list[wid][cnt + __popc(bal & ((1u << lane) - 1u))] = k0 + lane;
        cnt += __popc(bal);
        z = zn; cj = cjn; v = vn;
    }
    if (cnt > 0) {
        unsigned long long best = 0xFFFFFFFFull;
        for (int p = lane; p < cnt; p += 32) {
            int kk = s_list[wid][p];
            Geom B = d_geomK[kk];
            float2 zz = d_zK[kk];
            float oh = fminf(amax, zz.y) - fmaxf(amin, zz.x);
            float inter = rect_inter_bi(A, B) * oh;
            float un = fmaxf(va + d_ccK[kk].w - inter, EPSF);
            float iou = inter / un;
            if (iou > 0.f) {
                unsigned long long key =
                    (((unsigned long long)__float_as_uint(iou)) << 32) |
                    (unsigned long long)(0xFFFFFFFFu - (unsigned)d_joK[kk]);
                if (key > best) best = key;
            }
        }
#pragma unroll
        for (int o = 16; o > 0; o >>= 1) {
            unsigned long long vv = __shfl_xor_sync(0xffffffffu, best, o);
            if (vv > best) best = vv;
        }
        if (lane == 0 && best > 0xFFFFFFFFull) atomicMax(&s_best, best);
    }
    __syncthreads();
    if (threadIdx.x == 0) {
        unsigned long long key = s_best;
        float mo = __uint_as_float((unsigned)(key >> 32));
        int jb = (int)(0xFFFFFFFFu - (unsigned)(key & 0xFFFFFFFFull));
        mo = (mo > 0.75f) ? 1.0f : ((mo < 0.25f) ? 0.0f : mo);
        float lab = labels[i];
        float cp = 1.f / (1.f + expf(-cls[i]));
        out[i]         = (cp > 0.55f && lab > 0.55f) ? 1.0f : 0.0f;
        out[N + i]     = lab;
        out[2 * N + i] = mo;
        out[3 * N + i] = (float)jb;
    }
}

extern "C" void kernel_launch(void* const* d_in, const int* in_sizes, int n_in,
                              void* d_out, int out_size) {
    const float* labels = (const float*)d_in[0];
    const float* pred   = (const float*)d_in[1];
    const float* gt     = (const float*)d_in[2];
    const float* cls    = (const float*)d_in[3];
    if (n_in >= 3 && in_sizes[1] == 8 * N && in_sizes[2] == 7 * N) {
        pred = (const float*)d_in[2];
        gt   = (const float*)d_in[1];
    }
    float* out = (float*)d_out;

    prep_rank_kernel<<<N + 8, 256>>>(pred, gt, labels);
    nms_rows_kernel<<<N, 128>>>();
    nms_gs_kernel<<<1, 512>>>();
    iou_rows_kernel<<<N, 128>>>(labels, cls, out);
}